// round 15
// baseline (speedup 1.0000x reference)
#include <cuda_runtime.h>

#define BB 64
#define CC 16
#define HH 32
#define WW 512
#define NS 9    // shifts: off = s - 4

// Per-(pair,b,s,h) partials — pure writes, no zeroing / atomics.
__device__ float g_pnum[2][BB][NS][HH];
__device__ float g_pcnt[2][BB][NS][HH];
__device__ float g_bloss[BB];

typedef unsigned long long ull;

// Packed fp32x2 helpers (sm_103a FFMA2 — PTX only)
__device__ __forceinline__ ull pk2(float lo, float hi) {
    ull r; asm("mov.b64 %0, {%1, %2};" : "=l"(r) : "f"(lo), "f"(hi)); return r;
}
__device__ __forceinline__ float2 upk(ull v) {
    float2 f; asm("mov.b64 {%0, %1}, %2;" : "=f"(f.x), "=f"(f.y) : "l"(v)); return f;
}
__device__ __forceinline__ void ffma2(ull& d, ull a, ull b) {
    asm("fma.rn.f32x2 %0, %1, %2, %0;" : "+l"(d) : "l"(a), "l"(b));
}

__device__ __forceinline__ void load_mask4f(const char* __restrict__ m, size_t base,
                                            int mode, float out[4]) {
    if (mode == 0) {
        uchar4 v = *reinterpret_cast<const uchar4*>(m + base);
        out[0] = v.x ? 1.f : 0.f; out[1] = v.y ? 1.f : 0.f;
        out[2] = v.z ? 1.f : 0.f; out[3] = v.w ? 1.f : 0.f;
    } else if (mode == 1) {
        int4 v = *reinterpret_cast<const int4*>(reinterpret_cast<const int*>(m) + base);
        out[0] = v.x ? 1.f : 0.f; out[1] = v.y ? 1.f : 0.f;
        out[2] = v.z ? 1.f : 0.f; out[3] = v.w ? 1.f : 0.f;
    } else {
        float4 v = *reinterpret_cast<const float4*>(reinterpret_cast<const float*>(m) + base);
        out[0] = v.x != 0.f ? 1.f : 0.f; out[1] = v.y != 0.f ? 1.f : 0.f;
        out[2] = v.z != 0.f ? 1.f : 0.f; out[3] = v.w != 0.f ? 1.f : 0.f;
    }
}

// ---------------------------------------------------------------------------
// One CTA per (b,h). 128 threads, 4 consecutive w per thread.
// f windows come from THREE shifted warp-coalesced LDG.128s per channel —
// no cp.async, no f-smem, no hot-loop syncs. L1 merges the 3x line overlap.
// A row parked in thread-private smem (each thread touches only its own quad).
// ---------------------------------------------------------------------------
__global__ void __launch_bounds__(128, 4) loss_kernel(
    const float* __restrict__ A, const float* __restrict__ P,
    const float* __restrict__ Nt,
    const char* __restrict__ MA, const char* __restrict__ MP,
    const char* __restrict__ MN)
{
    __shared__ __align__(16) float sA[CC][WW];     // 32 KB, thread-private quads
    __shared__ __align__(16) float smF[2][WW];     // 4 KB (p/n masks as 0/1 f32)
    __shared__ float red_n[2][NS][4], red_c[2][NS][4];
    __shared__ unsigned int sflag[4];

    const int t  = threadIdx.x;
    const int l  = t & 31;
    const int b  = blockIdx.x >> 5;
    const int h  = blockIdx.x & 31;
    const int w0 = t * 4;
    const int e0 = (w0 - 4) & (WW - 1);
    const int e2 = (w0 + 4) & (WW - 1);

    const size_t row_off = ((size_t)b * CC * HH + h) * WW;
    const size_t mrow    = ((size_t)b * HH + h) * WW;

    // -- mask dtype sniff (identical deterministic result in every CTA) -----
    if (t < 64) {
        unsigned int w = reinterpret_cast<const unsigned int*>(MA)[t];
        unsigned int bf = __ballot_sync(0xffffffffu, w == 0x3F800000u);
        unsigned int bg = __ballot_sync(0xffffffffu, (w >> 8) != 0u);
        if (l == 0) { sflag[t >> 5] = bf; sflag[2 + (t >> 5)] = bg; }
    }
    __syncthreads();
    const int mode = (sflag[0] | sflag[1]) ? 2 : ((sflag[2] | sflag[3]) ? 0 : 1);

    // -- A row -> thread-private smem quads + packed Sa ----------------------
    float Sa[4];
    {
        ull s0 = pk2(0.f, 0.f), s1 = s0;
#pragma unroll
        for (int c = 0; c < CC; c++) {
            float4 v = *reinterpret_cast<const float4*>(A + row_off + (size_t)c * HH * WW + w0);
            *reinterpret_cast<float4*>(&sA[c][w0]) = v;
            ull va = pk2(v.x, v.y), vb = pk2(v.z, v.w);
            ffma2(s0, va, va); ffma2(s1, vb, vb);
        }
        float2 f = upk(s0); Sa[0] = f.x; Sa[1] = f.y;
        f = upk(s1);        Sa[2] = f.x; Sa[3] = f.y;
    }

    // -- masks: a-mask in registers; p/n masks to smem ------------------------
    float mam[4];
    load_mask4f(MA, mrow + w0, mode, mam);
    {
        float m4[4];
        load_mask4f(MP, mrow + w0, mode, m4);
        *reinterpret_cast<float4*>(&smF[0][w0]) = make_float4(m4[0], m4[1], m4[2], m4[3]);
        load_mask4f(MN, mrow + w0, mode, m4);
        *reinterpret_cast<float4*>(&smF[1][w0]) = make_float4(m4[0], m4[1], m4[2], m4[3]);
    }
    __syncthreads();   // smF visible; last CTA barrier before the final fold

#pragma unroll
    for (int pair = 0; pair < 2; pair++) {
        const float* __restrict__ F = pair ? Nt : P;

        // Accumulators: even s packed along j-pairs, odd s scalar; Sb in regs.
        ull  X2a[5], X2b[5];
        float Xo[4][4];
        ull  sbL[2], sbC[2], sbR[2];
        const ull z2 = pk2(0.f, 0.f);
#pragma unroll
        for (int m = 0; m < 5; m++) { X2a[m] = z2; X2b[m] = z2; }
#pragma unroll
        for (int j = 0; j < 4; j++)
#pragma unroll
            for (int m = 0; m < 4; m++) Xo[j][m] = 0.f;
        sbL[0] = sbL[1] = sbC[0] = sbC[1] = sbR[0] = sbR[1] = z2;

#pragma unroll
        for (int c = 0; c < CC; c++) {
            const float* __restrict__ src = F + row_off + (size_t)c * HH * WW;
            float4 W0 = *reinterpret_cast<const float4*>(src + e0);
            float4 W1 = *reinterpret_cast<const float4*>(src + w0);
            float4 W2 = *reinterpret_cast<const float4*>(src + e2);
            float4 a4 = *reinterpret_cast<const float4*>(&sA[c][w0]);

            ull wp[6] = {pk2(W0.x, W0.y), pk2(W0.z, W0.w),
                         pk2(W1.x, W1.y), pk2(W1.z, W1.w),
                         pk2(W2.x, W2.y), pk2(W2.z, W2.w)};
            ffma2(sbL[0], wp[0], wp[0]);
            ffma2(sbL[1], wp[1], wp[1]);
            ffma2(sbC[0], wp[2], wp[2]);
            ffma2(sbC[1], wp[3], wp[3]);
            ffma2(sbR[0], wp[4], wp[4]);
            ffma2(sbR[1], wp[5], wp[5]);

            const float win[12] = {W0.x, W0.y, W0.z, W0.w,
                                   W1.x, W1.y, W1.z, W1.w,
                                   W2.x, W2.y, W2.z, W2.w};
            const ull a01 = pk2(a4.x, a4.y);
            const ull a23 = pk2(a4.z, a4.w);

#pragma unroll
            for (int m = 0; m < 5; m++) {
                ffma2(X2a[m], a01, wp[4 - m]);
                ffma2(X2b[m], a23, wp[5 - m]);
            }
#pragma unroll
            for (int m = 0; m < 4; m++) {
                Xo[0][m] = fmaf(a4.x, win[7 - 2 * m],  Xo[0][m]);
                Xo[1][m] = fmaf(a4.y, win[8 - 2 * m],  Xo[1][m]);
                Xo[2][m] = fmaf(a4.z, win[9 - 2 * m],  Xo[2][m]);
                Xo[3][m] = fmaf(a4.w, win[10 - 2 * m], Xo[3][m]);
            }
        }

        // ---- pair epilogue (no CTA sync: swin from regs, mwin from smF) ----
        float X[4][NS];
#pragma unroll
        for (int m = 0; m < 5; m++) {
            float2 fa = upk(X2a[m]), fb = upk(X2b[m]);
            X[0][2 * m] = fa.x; X[1][2 * m] = fa.y;
            X[2][2 * m] = fb.x; X[3][2 * m] = fb.y;
        }
#pragma unroll
        for (int m = 0; m < 4; m++) {
            X[0][2 * m + 1] = Xo[0][m]; X[1][2 * m + 1] = Xo[1][m];
            X[2][2 * m + 1] = Xo[2][m]; X[3][2 * m + 1] = Xo[3][m];
        }

        float swin[12];
        { float2 f;
          f = upk(sbL[0]); swin[0]  = f.x; swin[1]  = f.y;
          f = upk(sbL[1]); swin[2]  = f.x; swin[3]  = f.y;
          f = upk(sbC[0]); swin[4]  = f.x; swin[5]  = f.y;
          f = upk(sbC[1]); swin[6]  = f.x; swin[7]  = f.y;
          f = upk(sbR[0]); swin[8]  = f.x; swin[9]  = f.y;
          f = upk(sbR[1]); swin[10] = f.x; swin[11] = f.y; }

        float4 M0 = *reinterpret_cast<const float4*>(&smF[pair][e0]);
        float4 M1 = *reinterpret_cast<const float4*>(&smF[pair][w0]);
        float4 M2 = *reinterpret_cast<const float4*>(&smF[pair][e2]);
        float mwin[12] = {M0.x, M0.y, M0.z, M0.w,
                          M1.x, M1.y, M1.z, M1.w,
                          M2.x, M2.y, M2.z, M2.w};

        float num[NS], cnt[NS];
#pragma unroll
        for (int s = 0; s < NS; s++) { num[s] = 0.f; cnt[s] = 0.f; }
#pragma unroll
        for (int j = 0; j < 4; j++)
#pragma unroll
            for (int s = 0; s < NS; s++) {
                const int idx = j + 8 - s;
                float v  = fmaf(-2.f, X[j][s], Sa[j]) + swin[idx];
                float mm = mam[j] * mwin[idx];
                num[s] = fmaf(mm, v, num[s]);
                cnt[s] += mm;
            }

#pragma unroll
        for (int s = 0; s < NS; s++) {
            float vn = num[s], vc = cnt[s];
            for (int o = 16; o > 0; o >>= 1) {
                vn += __shfl_down_sync(0xffffffffu, vn, o);
                vc += __shfl_down_sync(0xffffffffu, vc, o);
            }
            if (l == 0) {
                red_n[pair][s][t >> 5] = vn;
                red_c[pair][s][t >> 5] = vc;
            }
        }
    }

    __syncthreads();
    if (t < 36) {   // per-(b,h) partial slots (no atomics)
        const int pair = (t % 18) / 9, s = t % 9;
        if (t < 18) {
            g_pnum[pair][b][s][h] = red_n[pair][s][0] + red_n[pair][s][1] +
                                    red_n[pair][s][2] + red_n[pair][s][3];
        } else {
            g_pcnt[pair][b][s][h] = red_c[pair][s][0] + red_c[pair][s][1] +
                                    red_c[pair][s][2] + red_c[pair][s][3];
        }
    }
}

// ---------------------------------------------------------------------------
// Per-batch reduce: grid=BB, 9 warps; warp s reduces over h for both pairs.
// ---------------------------------------------------------------------------
__global__ void __launch_bounds__(288) perb_kernel() {
    __shared__ float d[2][NS];
    const int b = blockIdx.x;
    const int wid = threadIdx.x >> 5, lane = threadIdx.x & 31;

    if (wid < NS) {
        float n0 = g_pnum[0][b][wid][lane];
        float c0 = g_pcnt[0][b][wid][lane];
        float n1 = g_pnum[1][b][wid][lane];
        float c1 = g_pcnt[1][b][wid][lane];
#pragma unroll
        for (int o = 16; o > 0; o >>= 1) {
            n0 += __shfl_down_sync(0xffffffffu, n0, o);
            c0 += __shfl_down_sync(0xffffffffu, c0, o);
            n1 += __shfl_down_sync(0xffffffffu, n1, o);
            c1 += __shfl_down_sync(0xffffffffu, c1, o);
        }
        if (lane == 0) {
            d[0][wid] = n0 / (16.f * c0 + 0.001f);
            d[1][wid] = n1 / (16.f * c1 + 0.001f);
        }
    }
    __syncthreads();
    if (threadIdx.x == 0) {
        float lap = d[0][0], lan = d[1][0];
#pragma unroll
        for (int s = 1; s < NS; s++) {
            lap = fminf(lap, d[0][s]);
            lan = fminf(lan, d[1][s]);
        }
        g_bloss[b] = fmaxf(lap - lan + 0.15f, 0.f);
    }
}

// ---------------------------------------------------------------------------
__global__ void mean_kernel(float* __restrict__ out) {
    const int t = threadIdx.x;   // 64
    float v = g_bloss[t];
#pragma unroll
    for (int o = 16; o > 0; o >>= 1) v += __shfl_down_sync(0xffffffffu, v, o);
    __shared__ float warp0, warp1;
    if (t == 0)  warp0 = v;
    if (t == 32) warp1 = v;
    __syncthreads();
    if (t == 0) out[0] = (warp0 + warp1) / (float)BB;
}

// ---------------------------------------------------------------------------
extern "C" void kernel_launch(void* const* d_in, const int* in_sizes, int n_in,
                              void* d_out, int out_size) {
    const float* A  = (const float*)d_in[0];
    const float* P  = (const float*)d_in[1];
    const float* Nt = (const float*)d_in[2];
    const char*  MA = (const char*)d_in[3];
    const char*  MP = (const char*)d_in[4];
    const char*  MN = (const char*)d_in[5];
    float* out = (float*)d_out;

    loss_kernel<<<BB * HH, 128>>>(A, P, Nt, MA, MP, MN);
    perb_kernel<<<BB, 288>>>();
    mean_kernel<<<1, 64>>>(out);
}

// round 16
// speedup vs baseline: 1.2878x; 1.2878x over previous
#include <cuda_runtime.h>

#define BB 64
#define CC 16
#define HH 32
#define WW 512
#define NS 9    // shifts: off = s - 4
#define CT 4    // channels per cp.async tile
#define NBUF 4  // ring buffers

// Per-(pair,b,s,h) partials — pure writes, no zeroing / atomics.
__device__ float g_pnum[2][BB][NS][HH];
__device__ float g_pcnt[2][BB][NS][HH];
__device__ float g_bloss[BB];
__device__ int   g_done;   // last-block ticket; reset by last block each run

typedef unsigned long long ull;

__device__ __forceinline__ void cp_async16(unsigned int sdst, const void* gsrc) {
    asm volatile("cp.async.cg.shared.global [%0], [%1], 16;\n" :: "r"(sdst), "l"(gsrc));
}
__device__ __forceinline__ void cp_commit() {
    asm volatile("cp.async.commit_group;\n" ::: "memory");
}
template <int N> __device__ __forceinline__ void cp_wait() {
    asm volatile("cp.async.wait_group %0;\n" :: "n"(N) : "memory");
}

// Packed fp32x2 helpers (sm_103a FFMA2 — PTX only)
__device__ __forceinline__ ull pk2(float lo, float hi) {
    ull r; asm("mov.b64 %0, {%1, %2};" : "=l"(r) : "f"(lo), "f"(hi)); return r;
}
__device__ __forceinline__ float2 upk(ull v) {
    float2 f; asm("mov.b64 {%0, %1}, %2;" : "=f"(f.x), "=f"(f.y) : "l"(v)); return f;
}
__device__ __forceinline__ void ffma2(ull& d, ull a, ull b) {
    asm("fma.rn.f32x2 %0, %1, %2, %0;" : "+l"(d) : "l"(a), "l"(b));
}

__device__ __forceinline__ void load_mask4f(const char* __restrict__ m, size_t base,
                                            int mode, float out[4]) {
    if (mode == 0) {
        uchar4 v = *reinterpret_cast<const uchar4*>(m + base);
        out[0] = v.x ? 1.f : 0.f; out[1] = v.y ? 1.f : 0.f;
        out[2] = v.z ? 1.f : 0.f; out[3] = v.w ? 1.f : 0.f;
    } else if (mode == 1) {
        int4 v = *reinterpret_cast<const int4*>(reinterpret_cast<const int*>(m) + base);
        out[0] = v.x ? 1.f : 0.f; out[1] = v.y ? 1.f : 0.f;
        out[2] = v.z ? 1.f : 0.f; out[3] = v.w ? 1.f : 0.f;
    } else {
        float4 v = *reinterpret_cast<const float4*>(reinterpret_cast<const float*>(m) + base);
        out[0] = v.x != 0.f ? 1.f : 0.f; out[1] = v.y != 0.f ? 1.f : 0.f;
        out[2] = v.z != 0.f ? 1.f : 0.f; out[3] = v.w != 0.f ? 1.f : 0.f;
    }
}

// ---------------------------------------------------------------------------
// One CTA per (b,h). 128 threads, 4 consecutive w per thread.
// f rows streamed as 8 KB channel-tiles through a depth-3 cp.async ring.
// (R4 structure — verified fastest across 6 structural variants.)
// ---------------------------------------------------------------------------
__global__ void __launch_bounds__(128, 4) loss_kernel(
    const float* __restrict__ A, const float* __restrict__ P,
    const float* __restrict__ Nt,
    const char* __restrict__ MA, const char* __restrict__ MP,
    const char* __restrict__ MN)
{
    __shared__ __align__(16) float ring[NBUF][CT][WW];   // 32 KB
    __shared__ __align__(16) float sSb[WW];              // 2 KB
    __shared__ __align__(16) float smA[WW];              // 2 KB
    __shared__ __align__(16) float smF[2][WW];           // 4 KB
    __shared__ float red_n[2][NS][4], red_c[2][NS][4];
    __shared__ unsigned int sflag[4];

    const int t  = threadIdx.x;
    const int b  = blockIdx.x >> 5;
    const int h  = blockIdx.x & 31;
    const int w0 = t * 4;
    const int e0 = (w0 - 4) & (WW - 1);
    const int e2 = (w0 + 4) & (WW - 1);

    const size_t row_off = ((size_t)b * CC * HH + h) * WW;
    const size_t mrow    = ((size_t)b * HH + h) * WW;

    // -- mask dtype sniff (identical deterministic result in every CTA) -----
    if (t < 64) {
        unsigned int w = reinterpret_cast<const unsigned int*>(MA)[t];
        unsigned int bf = __ballot_sync(0xffffffffu, w == 0x3F800000u);
        unsigned int bg = __ballot_sync(0xffffffffu, (w >> 8) != 0u);
        if ((t & 31) == 0) { sflag[t >> 5] = bf; sflag[2 + (t >> 5)] = bg; }
    }

    auto issue_tile = [&](int k) {
        const float* F = (k >= 4) ? Nt : P;
        const int ct = k & 3, buf = k & 3;
#pragma unroll
        for (int cc = 0; cc < CT; cc++)
            cp_async16((unsigned int)__cvta_generic_to_shared(&ring[buf][cc][w0]),
                       F + row_off + (size_t)(ct * CT + cc) * HH * WW + w0);
        cp_commit();
    };
    issue_tile(0); issue_tile(1); issue_tile(2);
    __syncthreads();
    const int mode = (sflag[0] | sflag[1]) ? 2 : ((sflag[2] | sflag[3]) ? 0 : 1);

    // -- a row -> registers + packed Sa --------------------------------------
    float4 av[CC];
    ull Sa2[2] = {pk2(0.f, 0.f), pk2(0.f, 0.f)};
#pragma unroll
    for (int c = 0; c < CC; c++) {
        float4 v = *reinterpret_cast<const float4*>(A + row_off + (size_t)c * HH * WW + w0);
        av[c] = v;
        ull va = pk2(v.x, v.y), vb = pk2(v.z, v.w);
        ffma2(Sa2[0], va, va);
        ffma2(Sa2[1], vb, vb);
    }
    float Sa[4];
    { float2 f = upk(Sa2[0]); Sa[0] = f.x; Sa[1] = f.y;
      f = upk(Sa2[1]);        Sa[2] = f.x; Sa[3] = f.y; }

    // -- masks -> smem as 0/1 floats ------------------------------------------
    {
        float m4[4];
        load_mask4f(MA, mrow + w0, mode, m4);
        *reinterpret_cast<float4*>(&smA[w0]) = make_float4(m4[0], m4[1], m4[2], m4[3]);
        load_mask4f(MP, mrow + w0, mode, m4);
        *reinterpret_cast<float4*>(&smF[0][w0]) = make_float4(m4[0], m4[1], m4[2], m4[3]);
        load_mask4f(MN, mrow + w0, mode, m4);
        *reinterpret_cast<float4*>(&smF[1][w0]) = make_float4(m4[0], m4[1], m4[2], m4[3]);
    }

    // Accumulators: even s packed along j-pairs, odd s scalar.
    ull  X2a[5], X2b[5];
    float Xo[4][4];
    ull  sb2[2];
    const ull z2 = pk2(0.f, 0.f);
#pragma unroll
    for (int m = 0; m < 5; m++) { X2a[m] = z2; X2b[m] = z2; }
#pragma unroll
    for (int j = 0; j < 4; j++)
#pragma unroll
        for (int m = 0; m < 4; m++) Xo[j][m] = 0.f;
    sb2[0] = z2; sb2[1] = z2;

    // -- main tile loop: 8 tiles = (P 0..3, N 0..3) ----------------------------
#pragma unroll
    for (int k = 0; k < 8; k++) {
        if (k <= 5)      cp_wait<2>();
        else if (k == 6) cp_wait<1>();
        else             cp_wait<0>();
        __syncthreads();
        if (k < 5) issue_tile(k + 3);

        const int pair = k >> 2, ct = k & 3, buf = k & 3;

#pragma unroll
        for (int cc = 0; cc < CT; cc++) {
            const int c = ct * CT + cc;
            float4 W0 = *reinterpret_cast<const float4*>(&ring[buf][cc][e0]);
            float4 W1 = *reinterpret_cast<const float4*>(&ring[buf][cc][w0]);
            float4 W2 = *reinterpret_cast<const float4*>(&ring[buf][cc][e2]);

            ull wp[6] = {pk2(W0.x, W0.y), pk2(W0.z, W0.w),
                         pk2(W1.x, W1.y), pk2(W1.z, W1.w),
                         pk2(W2.x, W2.y), pk2(W2.z, W2.w)};
            ffma2(sb2[0], wp[2], wp[2]);
            ffma2(sb2[1], wp[3], wp[3]);

            const float win[12] = {W0.x, W0.y, W0.z, W0.w,
                                   W1.x, W1.y, W1.z, W1.w,
                                   W2.x, W2.y, W2.z, W2.w};
            const ull a01 = pk2(av[c].x, av[c].y);
            const ull a23 = pk2(av[c].z, av[c].w);

#pragma unroll
            for (int m = 0; m < 5; m++) {
                ffma2(X2a[m], a01, wp[4 - m]);
                ffma2(X2b[m], a23, wp[5 - m]);
            }
#pragma unroll
            for (int m = 0; m < 4; m++) {
                Xo[0][m] = fmaf(av[c].x, win[7 - 2 * m],  Xo[0][m]);
                Xo[1][m] = fmaf(av[c].y, win[8 - 2 * m],  Xo[1][m]);
                Xo[2][m] = fmaf(av[c].z, win[9 - 2 * m],  Xo[2][m]);
                Xo[3][m] = fmaf(av[c].w, win[10 - 2 * m], Xo[3][m]);
            }
        }

        if (ct == 3) {   // pair epilogue
            { float2 f0 = upk(sb2[0]), f1 = upk(sb2[1]);
              *reinterpret_cast<float4*>(&sSb[w0]) = make_float4(f0.x, f0.y, f1.x, f1.y); }
            __syncthreads();

            float X[4][NS];
#pragma unroll
            for (int m = 0; m < 5; m++) {
                float2 fa = upk(X2a[m]), fb = upk(X2b[m]);
                X[0][2 * m] = fa.x; X[1][2 * m] = fa.y;
                X[2][2 * m] = fb.x; X[3][2 * m] = fb.y;
            }
#pragma unroll
            for (int m = 0; m < 4; m++) {
                X[0][2 * m + 1] = Xo[0][m]; X[1][2 * m + 1] = Xo[1][m];
                X[2][2 * m + 1] = Xo[2][m]; X[3][2 * m + 1] = Xo[3][m];
            }

            float4 S0 = *reinterpret_cast<const float4*>(&sSb[e0]);
            float4 S1 = *reinterpret_cast<const float4*>(&sSb[w0]);
            float4 S2 = *reinterpret_cast<const float4*>(&sSb[e2]);
            float swin[12] = {S0.x, S0.y, S0.z, S0.w,
                              S1.x, S1.y, S1.z, S1.w,
                              S2.x, S2.y, S2.z, S2.w};
            float4 M0 = *reinterpret_cast<const float4*>(&smF[pair][e0]);
            float4 M1 = *reinterpret_cast<const float4*>(&smF[pair][w0]);
            float4 M2 = *reinterpret_cast<const float4*>(&smF[pair][e2]);
            float mwin[12] = {M0.x, M0.y, M0.z, M0.w,
                              M1.x, M1.y, M1.z, M1.w,
                              M2.x, M2.y, M2.z, M2.w};
            float4 ma4 = *reinterpret_cast<const float4*>(&smA[w0]);
            float mam[4] = {ma4.x, ma4.y, ma4.z, ma4.w};

            float num[NS], cnt[NS];
#pragma unroll
            for (int s = 0; s < NS; s++) { num[s] = 0.f; cnt[s] = 0.f; }
#pragma unroll
            for (int j = 0; j < 4; j++)
#pragma unroll
                for (int s = 0; s < NS; s++) {
                    const int idx = j + 8 - s;
                    float v  = fmaf(-2.f, X[j][s], Sa[j]) + swin[idx];
                    float mm = mam[j] * mwin[idx];
                    num[s] = fmaf(mm, v, num[s]);
                    cnt[s] += mm;
                }

#pragma unroll
            for (int s = 0; s < NS; s++) {
                float vn = num[s], vc = cnt[s];
                for (int o = 16; o > 0; o >>= 1) {
                    vn += __shfl_down_sync(0xffffffffu, vn, o);
                    vc += __shfl_down_sync(0xffffffffu, vc, o);
                }
                if ((t & 31) == 0) {
                    red_n[pair][s][t >> 5] = vn;
                    red_c[pair][s][t >> 5] = vc;
                }
            }

            // reset accumulators for next pair
#pragma unroll
            for (int m = 0; m < 5; m++) { X2a[m] = z2; X2b[m] = z2; }
#pragma unroll
            for (int j = 0; j < 4; j++)
#pragma unroll
                for (int m = 0; m < 4; m++) Xo[j][m] = 0.f;
            sb2[0] = z2; sb2[1] = z2;
        }
    }

    __syncthreads();
    if (t < 36) {   // per-(b,h) partial slots (no atomics)
        const int pair = (t % 18) / 9, s = t % 9;
        if (t < 18) {
            g_pnum[pair][b][s][h] = red_n[pair][s][0] + red_n[pair][s][1] +
                                    red_n[pair][s][2] + red_n[pair][s][3];
        } else {
            g_pcnt[pair][b][s][h] = red_c[pair][s][0] + red_c[pair][s][1] +
                                    red_c[pair][s][2] + red_c[pair][s][3];
        }
    }
}

// ---------------------------------------------------------------------------
// Per-batch reduce + fused mean: grid=BB; warp s reduces over h for both
// pairs; block computes its g_bloss[b]; the LAST block (ticket) reduces the
// 64 per-batch losses and writes the scalar. Counter self-resets for graph
// replay; fully deterministic.
// ---------------------------------------------------------------------------
__global__ void __launch_bounds__(288) perb_kernel(float* __restrict__ out) {
    __shared__ float d[2][NS];
    __shared__ int ticket;
    __shared__ float wsum[2];
    const int b = blockIdx.x;
    const int wid = threadIdx.x >> 5, lane = threadIdx.x & 31;

    if (wid < NS) {
        float n0 = g_pnum[0][b][wid][lane];
        float c0 = g_pcnt[0][b][wid][lane];
        float n1 = g_pnum[1][b][wid][lane];
        float c1 = g_pcnt[1][b][wid][lane];
#pragma unroll
        for (int o = 16; o > 0; o >>= 1) {
            n0 += __shfl_down_sync(0xffffffffu, n0, o);
            c0 += __shfl_down_sync(0xffffffffu, c0, o);
            n1 += __shfl_down_sync(0xffffffffu, n1, o);
            c1 += __shfl_down_sync(0xffffffffu, c1, o);
        }
        if (lane == 0) {
            d[0][wid] = n0 / (16.f * c0 + 0.001f);
            d[1][wid] = n1 / (16.f * c1 + 0.001f);
        }
    }
    __syncthreads();
    if (threadIdx.x == 0) {
        float lap = d[0][0], lan = d[1][0];
#pragma unroll
        for (int s = 1; s < NS; s++) {
            lap = fminf(lap, d[0][s]);
            lan = fminf(lan, d[1][s]);
        }
        g_bloss[b] = fmaxf(lap - lan + 0.15f, 0.f);
        __threadfence();
        ticket = atomicAdd(&g_done, 1);
    }
    __syncthreads();

    if (ticket == BB - 1) {           // last block folds the mean
        __threadfence();              // acquire: all g_bloss writes visible
        if (threadIdx.x < BB) {
            float v = g_bloss[threadIdx.x];
#pragma unroll
            for (int o = 16; o > 0; o >>= 1)
                v += __shfl_down_sync(0xffffffffu, v, o);
            if ((threadIdx.x & 31) == 0) wsum[threadIdx.x >> 5] = v;
        }
        __syncthreads();
        if (threadIdx.x == 0) {
            out[0] = (wsum[0] + wsum[1]) / (float)BB;
            g_done = 0;               // reset for next graph replay
        }
    }
}

// ---------------------------------------------------------------------------
extern "C" void kernel_launch(void* const* d_in, const int* in_sizes, int n_in,
                              void* d_out, int out_size) {
    const float* A  = (const float*)d_in[0];
    const float* P  = (const float*)d_in[1];
    const float* Nt = (const float*)d_in[2];
    const char*  MA = (const char*)d_in[3];
    const char*  MP = (const char*)d_in[4];
    const char*  MN = (const char*)d_in[5];
    float* out = (float*)d_out;

    loss_kernel<<<BB * HH, 128>>>(A, P, Nt, MA, MP, MN);
    perb_kernel<<<BB, 288>>>(out);
}